// round 11
// baseline (speedup 1.0000x reference)
#include <cuda_runtime.h>
#include <math.h>

#define H 1024
#define S 65536
#define NB_VPART 128            // 8 rows of W each
#define NB_SCORES 2048          // 32 rows of enc each, FOUR rows per warp
#define NB_NORM 256

// ---------------- scratch (no allocations allowed) ----------------
__device__ float    g_vpart[NB_VPART * H]; // 128 partial v vectors (512 KB)
__device__ float    g_v[H];                // v = W^T @ hidden
__device__ float    g_scores[S];           // raw scores
__device__ float2   g_bpart[NB_SCORES];    // per-CTA (max, sumexp)
__device__ unsigned g_Mu;                  // global max, order-encoded uint

// ordered-uint encoding of float (monotonic): deterministic atomicMax
__device__ __forceinline__ unsigned encf(float f) {
    unsigned b = __float_as_uint(f);
    return (b & 0x80000000u) ? ~b : (b | 0x80000000u);
}
__device__ __forceinline__ float decf(unsigned u) {
    unsigned b = (u & 0x80000000u) ? (u & 0x7fffffffu) : ~u;
    return __uint_as_float(b);
}

__device__ __forceinline__ float4 ldcs4(const float4* p) {
    return __ldcs(p);                     // streaming load (evict-first)
}

// =====================================================================
// kernel 1: partial v. 128 blocks x 256 thr; block b sums rows
// [8b, 8b+8). 8 independent float4 loads per thread (MLP=8).
// Also resets g_Mu for this graph replay (consumed 2 kernels later).
// =====================================================================
__global__ void __launch_bounds__(256) k_vpart(const float* __restrict__ hidden,
                                               const float* __restrict__ W) {
    int t  = threadIdx.x;                 // float4 column
    if (blockIdx.x == 0 && t == 0) g_Mu = 0u;   // enc(-inf) lower bound
    int r0 = blockIdx.x * 8;

    float h[8];
    float4 w[8];
#pragma unroll
    for (int i = 0; i < 8; i++) h[i] = __ldg(&hidden[r0 + i]);
#pragma unroll
    for (int i = 0; i < 8; i++)
        w[i] = ldcs4(reinterpret_cast<const float4*>(W + (size_t)(r0 + i) * H) + t);

    float4 acc = make_float4(0.f, 0.f, 0.f, 0.f);
#pragma unroll
    for (int i = 0; i < 8; i++) {
        acc.x += h[i] * w[i].x; acc.y += h[i] * w[i].y;
        acc.z += h[i] * w[i].z; acc.w += h[i] * w[i].w;
    }
    reinterpret_cast<float4*>(g_vpart + (size_t)blockIdx.x * H)[t] = acc;
}

// =====================================================================
// kernel 2: reduce 128 partials -> g_v. 16 blocks x 256 thr.  (PDL)
// =====================================================================
__global__ void __launch_bounds__(256) k_vreduce() {
#if __CUDA_ARCH__ >= 900
    cudaGridDependencySynchronize();
#endif
    __shared__ float4 sm[256];
    int t  = threadIdx.x;
    int c  = t & 15;                      // float4 col within block
    int pg = t >> 4;                      // partial group
    int col = (blockIdx.x * 16 + c);      // global float4 col [0,256)

    float4 acc = make_float4(0.f, 0.f, 0.f, 0.f);
#pragma unroll
    for (int p = pg; p < NB_VPART; p += 16) {     // 8 partials, MLP=8
        float4 x = reinterpret_cast<const float4*>(g_vpart)[(size_t)p * 256 + col];
        acc.x += x.x; acc.y += x.y; acc.z += x.z; acc.w += x.w;
    }
    sm[t] = acc;
    __syncthreads();
#pragma unroll
    for (int off = 128; off >= 16; off >>= 1) {
        if (t < off) {
            float4 a = sm[t], b = sm[t + off];
            a.x += b.x; a.y += b.y; a.z += b.z; a.w += b.w;
            sm[t] = a;
        }
        __syncthreads();
    }
    if (t < 16) reinterpret_cast<float4*>(g_v)[col] = sm[t];
}

// =====================================================================
// kernel 3: scores = enc @ v + per-block (m,s) + atomicMax global M.
// 2048 blocks x 256 thr, FOUR rows per warp with ALL 32 float4 loads
// issued up front (MLP=32, 16 KB in flight per warp) and BEFORE the
// grid-dependency sync.  (PDL)
// =====================================================================
__global__ void __launch_bounds__(256) k_scores(const float* __restrict__ enc) {
    __shared__ float4 sv[256];
    __shared__ float  rowv[32];
    int t = threadIdx.x;
    int warp = t >> 5, lane = t & 31;

    int row0 = (blockIdx.x << 5) + (warp << 2);         // this warp's 4 rows
    const float4* e0 = reinterpret_cast<const float4*>(enc + (size_t)row0 * H);

    // ---- prefetch FOUR rows (32 independent LDG.128, pre-sync) ----
    float4 a[8], c[8], d[8], f[8];
#pragma unroll
    for (int k = 0; k < 8; k++) a[k] = ldcs4(e0 + 0 * 256 + k * 32 + lane);
#pragma unroll
    for (int k = 0; k < 8; k++) c[k] = ldcs4(e0 + 1 * 256 + k * 32 + lane);
#pragma unroll
    for (int k = 0; k < 8; k++) d[k] = ldcs4(e0 + 2 * 256 + k * 32 + lane);
#pragma unroll
    for (int k = 0; k < 8; k++) f[k] = ldcs4(e0 + 3 * 256 + k * 32 + lane);

#if __CUDA_ARCH__ >= 900
    cudaGridDependencySynchronize();      // now wait for g_v
#endif
    sv[t] = reinterpret_cast<const float4*>(g_v)[t];
    __syncthreads();

    float acc0 = 0.f, acc1 = 0.f, acc2 = 0.f, acc3 = 0.f;
#pragma unroll
    for (int k = 0; k < 8; k++) {
        float4 b = sv[k * 32 + lane];
        acc0 += a[k].x*b.x + a[k].y*b.y + a[k].z*b.z + a[k].w*b.w;
        acc1 += c[k].x*b.x + c[k].y*b.y + c[k].z*b.z + c[k].w*b.w;
        acc2 += d[k].x*b.x + d[k].y*b.y + d[k].z*b.z + d[k].w*b.w;
        acc3 += f[k].x*b.x + f[k].y*b.y + f[k].z*b.z + f[k].w*b.w;
    }
#pragma unroll
    for (int o = 16; o; o >>= 1) {
        acc0 += __shfl_xor_sync(0xffffffffu, acc0, o);
        acc1 += __shfl_xor_sync(0xffffffffu, acc1, o);
        acc2 += __shfl_xor_sync(0xffffffffu, acc2, o);
        acc3 += __shfl_xor_sync(0xffffffffu, acc3, o);
    }
    if (lane == 0) {
        g_scores[row0]     = acc0;
        g_scores[row0 + 1] = acc1;
        g_scores[row0 + 2] = acc2;
        g_scores[row0 + 3] = acc3;
        rowv[(warp << 2)]     = acc0;
        rowv[(warp << 2) + 1] = acc1;
        rowv[(warp << 2) + 2] = acc2;
        rowv[(warp << 2) + 3] = acc3;
    }
    __syncthreads();

    // warp 0: block (m,s) over 32 row scores, fully lane-parallel
    if (warp == 0) {
        float x = rowv[lane];
        float m = x;
#pragma unroll
        for (int o = 16; o; o >>= 1) m = fmaxf(m, __shfl_xor_sync(0xffffffffu, m, o));
        float p = __expf(x - m);
#pragma unroll
        for (int o = 16; o; o >>= 1) p += __shfl_xor_sync(0xffffffffu, p, o);
        if (lane == 0) {
            g_bpart[blockIdx.x] = make_float2(m, p);
            atomicMax(&g_Mu, encf(m));    // order-independent => deterministic
        }
    }
}

// =====================================================================
// kernel 4: normalize. M from g_Mu; each of 256 blocks redundantly sums
// s_i*exp(m_i-M) over 2048 partials (8/thread, shfl, 2 barriers),
// then normalizes its 256-element slice (scalar coalesced).  (PDL)
// =====================================================================
__global__ void __launch_bounds__(256) k_norm(float* __restrict__ out) {
    __shared__ float swarp[8];
    __shared__ float sS;
    int t = threadIdx.x;
    int warp = t >> 5, lane = t & 31;
#if __CUDA_ARCH__ >= 900
    cudaGridDependencySynchronize();
#endif
    float M = decf(g_Mu);

    float s_loc = 0.f;
#pragma unroll
    for (int k = 0; k < NB_SCORES / 256; k++) {     // 8 partials per thread
        float2 p = g_bpart[k * 256 + t];
        s_loc += p.y * __expf(p.x - M);
    }
#pragma unroll
    for (int o = 16; o; o >>= 1) s_loc += __shfl_xor_sync(0xffffffffu, s_loc, o);
    if (lane == 0) swarp[warp] = s_loc;
    __syncthreads();
    if (warp == 0) {
        float v = (lane < 8) ? swarp[lane] : 0.f;
#pragma unroll
        for (int o = 4; o; o >>= 1) v += __shfl_xor_sync(0xffffffffu, v, o);
        if (lane == 0) sS = v;
    }
    __syncthreads();
    float inv = 1.f / sS;

    int i = blockIdx.x * 256 + t;                   // scalar, coalesced
    float s = g_scores[i];
    __stcs(&out[i], __expf(s - M) * inv);
}

// ---------------- launch (PDL on dependent edges) ----------------
static void launch_pdl(void* fn, dim3 grid, dim3 block, void** args) {
    cudaLaunchConfig_t cfg = {};
    cfg.gridDim = grid;
    cfg.blockDim = block;
    cfg.dynamicSmemBytes = 0;
    cfg.stream = 0;
    cudaLaunchAttribute attr[1];
    attr[0].id = cudaLaunchAttributeProgrammaticStreamSerialization;
    attr[0].val.programmaticStreamSerializationAllowed = 1;
    cfg.attrs = attr;
    cfg.numAttrs = 1;
    cudaLaunchKernelExC(&cfg, fn, args);
}

extern "C" void kernel_launch(void* const* d_in, const int* in_sizes, int n_in,
                              void* d_out, int out_size) {
    const float* hidden = (const float*)d_in[0];   // [H]
    const float* enc    = (const float*)d_in[1];   // [S, H]
    const float* W      = (const float*)d_in[2];   // [H, H]
    // d_in[3] = b : dropped — softmax is shift-invariant to b.hidden
    float* out = (float*)d_out;                    // [S]

    k_vpart<<<NB_VPART, 256>>>(hidden, W);

    void* a1[] = {};
    launch_pdl((void*)k_vreduce, dim3(16), dim3(256), a1);

    void* a2[] = {(void*)&enc};
    launch_pdl((void*)k_scores, dim3(NB_SCORES), dim3(256), a2);

    void* a3[] = {(void*)&out};
    launch_pdl((void*)k_norm, dim3(NB_NORM), dim3(256), a3);
}

// round 12
// speedup vs baseline: 1.1231x; 1.1231x over previous
#include <cuda_runtime.h>
#include <math.h>

#define H 1024
#define S 65536
#define NB_VPART 128            // 8 rows of W each
#define NB_SCORES 4096          // 16 rows of enc each, TWO rows per warp
#define NB_NORM 256

// ---------------- scratch (no allocations allowed) ----------------
__device__ float    g_vpart[NB_VPART * H]; // 128 partial v vectors (512 KB)
__device__ float    g_v[H];                // v = W^T @ hidden
__device__ float    g_scores[S];           // raw scores
__device__ float2   g_bpart[NB_SCORES];    // per-CTA (max, sumexp)
__device__ unsigned g_Mu;                  // global max, order-encoded uint

// ordered-uint encoding of float (monotonic): deterministic atomicMax
__device__ __forceinline__ unsigned encf(float f) {
    unsigned b = __float_as_uint(f);
    return (b & 0x80000000u) ? ~b : (b | 0x80000000u);
}
__device__ __forceinline__ float decf(unsigned u) {
    unsigned b = (u & 0x80000000u) ? (u & 0x7fffffffu) : ~u;
    return __uint_as_float(b);
}

__device__ __forceinline__ float4 ldcs4(const float4* p) {
    return __ldcs(p);                     // streaming load (evict-first)
}

// =====================================================================
// kernel 1: partial v. 128 blocks x 256 thr; block b sums rows
// [8b, 8b+8). 8 independent float4 loads per thread (MLP=8).
// Also resets g_Mu for this graph replay (consumed 2 kernels later).
// =====================================================================
__global__ void __launch_bounds__(256) k_vpart(const float* __restrict__ hidden,
                                               const float* __restrict__ W) {
    int t  = threadIdx.x;                 // float4 column
    if (blockIdx.x == 0 && t == 0) g_Mu = 0u;   // enc(-inf) lower bound
    int r0 = blockIdx.x * 8;

    float h[8];
    float4 w[8];
#pragma unroll
    for (int i = 0; i < 8; i++) h[i] = __ldg(&hidden[r0 + i]);
#pragma unroll
    for (int i = 0; i < 8; i++)
        w[i] = ldcs4(reinterpret_cast<const float4*>(W + (size_t)(r0 + i) * H) + t);

    float4 acc = make_float4(0.f, 0.f, 0.f, 0.f);
#pragma unroll
    for (int i = 0; i < 8; i++) {
        acc.x += h[i] * w[i].x; acc.y += h[i] * w[i].y;
        acc.z += h[i] * w[i].z; acc.w += h[i] * w[i].w;
    }
    reinterpret_cast<float4*>(g_vpart + (size_t)blockIdx.x * H)[t] = acc;
}

// =====================================================================
// kernel 2: reduce 128 partials -> g_v. 16 blocks x 256 thr.  (PDL)
// =====================================================================
__global__ void __launch_bounds__(256) k_vreduce() {
#if __CUDA_ARCH__ >= 900
    cudaGridDependencySynchronize();
#endif
    __shared__ float4 sm[256];
    int t  = threadIdx.x;
    int c  = t & 15;                      // float4 col within block
    int pg = t >> 4;                      // partial group
    int col = (blockIdx.x * 16 + c);      // global float4 col [0,256)

    float4 acc = make_float4(0.f, 0.f, 0.f, 0.f);
#pragma unroll
    for (int p = pg; p < NB_VPART; p += 16) {     // 8 partials, MLP=8
        float4 x = reinterpret_cast<const float4*>(g_vpart)[(size_t)p * 256 + col];
        acc.x += x.x; acc.y += x.y; acc.z += x.z; acc.w += x.w;
    }
    sm[t] = acc;
    __syncthreads();
#pragma unroll
    for (int off = 128; off >= 16; off >>= 1) {
        if (t < off) {
            float4 a = sm[t], b = sm[t + off];
            a.x += b.x; a.y += b.y; a.z += b.z; a.w += b.w;
            sm[t] = a;
        }
        __syncthreads();
    }
    if (t < 16) reinterpret_cast<float4*>(g_v)[col] = sm[t];
}

// =====================================================================
// kernel 3: scores = enc @ v + per-block (m,s) + atomicMax global M.
// 4096 blocks x 256 thr, TWO rows per warp with ALL 16 float4 loads
// issued up front (MLP=16, 8 KB in flight per warp) and BEFORE the
// grid-dependency sync — measured optimum of the MLP curve.  (PDL)
// =====================================================================
__global__ void __launch_bounds__(256) k_scores(const float* __restrict__ enc) {
    __shared__ float4 sv[256];
    __shared__ float  rowv[16];
    int t = threadIdx.x;
    int warp = t >> 5, lane = t & 31;

    int row0 = (blockIdx.x << 4) + (warp << 1);         // this warp's 2 rows
    const float4* e0 = reinterpret_cast<const float4*>(enc + (size_t)row0 * H);
    const float4* e1 = e0 + (H / 4);

    // ---- prefetch BOTH rows (16 independent LDG.128, pre-sync) ----
    float4 a0 = ldcs4(e0 + 0 * 32 + lane);
    float4 a1 = ldcs4(e0 + 1 * 32 + lane);
    float4 a2 = ldcs4(e0 + 2 * 32 + lane);
    float4 a3 = ldcs4(e0 + 3 * 32 + lane);
    float4 a4 = ldcs4(e0 + 4 * 32 + lane);
    float4 a5 = ldcs4(e0 + 5 * 32 + lane);
    float4 a6 = ldcs4(e0 + 6 * 32 + lane);
    float4 a7 = ldcs4(e0 + 7 * 32 + lane);
    float4 c0 = ldcs4(e1 + 0 * 32 + lane);
    float4 c1 = ldcs4(e1 + 1 * 32 + lane);
    float4 c2 = ldcs4(e1 + 2 * 32 + lane);
    float4 c3 = ldcs4(e1 + 3 * 32 + lane);
    float4 c4 = ldcs4(e1 + 4 * 32 + lane);
    float4 c5 = ldcs4(e1 + 5 * 32 + lane);
    float4 c6 = ldcs4(e1 + 6 * 32 + lane);
    float4 c7 = ldcs4(e1 + 7 * 32 + lane);

#if __CUDA_ARCH__ >= 900
    cudaGridDependencySynchronize();      // now wait for g_v
#endif
    sv[t] = reinterpret_cast<const float4*>(g_v)[t];
    __syncthreads();

    float acc0 = 0.f, acc1 = 0.f;
    {
        float4 b;
        b = sv[0 * 32 + lane];
        acc0 += a0.x*b.x + a0.y*b.y + a0.z*b.z + a0.w*b.w;
        acc1 += c0.x*b.x + c0.y*b.y + c0.z*b.z + c0.w*b.w;
        b = sv[1 * 32 + lane];
        acc0 += a1.x*b.x + a1.y*b.y + a1.z*b.z + a1.w*b.w;
        acc1 += c1.x*b.x + c1.y*b.y + c1.z*b.z + c1.w*b.w;
        b = sv[2 * 32 + lane];
        acc0 += a2.x*b.x + a2.y*b.y + a2.z*b.z + a2.w*b.w;
        acc1 += c2.x*b.x + c2.y*b.y + c2.z*b.z + c2.w*b.w;
        b = sv[3 * 32 + lane];
        acc0 += a3.x*b.x + a3.y*b.y + a3.z*b.z + a3.w*b.w;
        acc1 += c3.x*b.x + c3.y*b.y + c3.z*b.z + c3.w*b.w;
        b = sv[4 * 32 + lane];
        acc0 += a4.x*b.x + a4.y*b.y + a4.z*b.z + a4.w*b.w;
        acc1 += c4.x*b.x + c4.y*b.y + c4.z*b.z + c4.w*b.w;
        b = sv[5 * 32 + lane];
        acc0 += a5.x*b.x + a5.y*b.y + a5.z*b.z + a5.w*b.w;
        acc1 += c5.x*b.x + c5.y*b.y + c5.z*b.z + c5.w*b.w;
        b = sv[6 * 32 + lane];
        acc0 += a6.x*b.x + a6.y*b.y + a6.z*b.z + a6.w*b.w;
        acc1 += c6.x*b.x + c6.y*b.y + c6.z*b.z + c6.w*b.w;
        b = sv[7 * 32 + lane];
        acc0 += a7.x*b.x + a7.y*b.y + a7.z*b.z + a7.w*b.w;
        acc1 += c7.x*b.x + c7.y*b.y + c7.z*b.z + c7.w*b.w;
    }
#pragma unroll
    for (int o = 16; o; o >>= 1) {
        acc0 += __shfl_xor_sync(0xffffffffu, acc0, o);
        acc1 += __shfl_xor_sync(0xffffffffu, acc1, o);
    }
    if (lane == 0) {
        g_scores[row0]     = acc0;
        g_scores[row0 + 1] = acc1;
        rowv[(warp << 1)]     = acc0;
        rowv[(warp << 1) + 1] = acc1;
    }
    __syncthreads();

    // warp 0: block (m,s) over 16 row scores, lane-parallel
    if (warp == 0) {
        float x = (lane < 16) ? rowv[lane] : -INFINITY;
        float m = x;
#pragma unroll
        for (int o = 8; o; o >>= 1) m = fmaxf(m, __shfl_xor_sync(0xffffffffu, m, o));
        float p = (lane < 16) ? __expf(x - m) : 0.f;
#pragma unroll
        for (int o = 8; o; o >>= 1) p += __shfl_xor_sync(0xffffffffu, p, o);
        if (lane == 0) {
            g_bpart[blockIdx.x] = make_float2(m, p);
            atomicMax(&g_Mu, encf(m));    // order-independent => deterministic
        }
    }
}

// =====================================================================
// kernel 4: normalize. M from g_Mu; each of 256 blocks redundantly sums
// s_i*exp(m_i-M) over 4096 partials (16/thread, shfl, 2 barriers),
// then normalizes its 256-element slice (scalar coalesced).  (PDL)
// =====================================================================
__global__ void __launch_bounds__(256) k_norm(float* __restrict__ out) {
    __shared__ float swarp[8];
    __shared__ float sS;
    int t = threadIdx.x;
    int warp = t >> 5, lane = t & 31;
#if __CUDA_ARCH__ >= 900
    cudaGridDependencySynchronize();
#endif
    float M = decf(g_Mu);

    float s_loc = 0.f;
#pragma unroll
    for (int k = 0; k < NB_SCORES / 256; k++) {     // 16 partials per thread
        float2 p = g_bpart[k * 256 + t];
        s_loc += p.y * __expf(p.x - M);
    }
#pragma unroll
    for (int o = 16; o; o >>= 1) s_loc += __shfl_xor_sync(0xffffffffu, s_loc, o);
    if (lane == 0) swarp[warp] = s_loc;
    __syncthreads();
    if (warp == 0) {
        float v = (lane < 8) ? swarp[lane] : 0.f;
#pragma unroll
        for (int o = 4; o; o >>= 1) v += __shfl_xor_sync(0xffffffffu, v, o);
        if (lane == 0) sS = v;
    }
    __syncthreads();
    float inv = 1.f / sS;

    int i = blockIdx.x * 256 + t;                   // scalar, coalesced
    float s = g_scores[i];
    __stcs(&out[i], __expf(s - M) * inv);
}

// ---------------- launch (PDL on dependent edges) ----------------
static void launch_pdl(void* fn, dim3 grid, dim3 block, void** args) {
    cudaLaunchConfig_t cfg = {};
    cfg.gridDim = grid;
    cfg.blockDim = block;
    cfg.dynamicSmemBytes = 0;
    cfg.stream = 0;
    cudaLaunchAttribute attr[1];
    attr[0].id = cudaLaunchAttributeProgrammaticStreamSerialization;
    attr[0].val.programmaticStreamSerializationAllowed = 1;
    cfg.attrs = attr;
    cfg.numAttrs = 1;
    cudaLaunchKernelExC(&cfg, fn, args);
}

extern "C" void kernel_launch(void* const* d_in, const int* in_sizes, int n_in,
                              void* d_out, int out_size) {
    const float* hidden = (const float*)d_in[0];   // [H]
    const float* enc    = (const float*)d_in[1];   // [S, H]
    const float* W      = (const float*)d_in[2];   // [H, H]
    // d_in[3] = b : dropped — softmax is shift-invariant to b.hidden
    float* out = (float*)d_out;                    // [S]

    k_vpart<<<NB_VPART, 256>>>(hidden, W);

    void* a1[] = {};
    launch_pdl((void*)k_vreduce, dim3(16), dim3(256), a1);

    void* a2[] = {(void*)&enc};
    launch_pdl((void*)k_scores, dim3(NB_SCORES), dim3(256), a2);

    void* a3[] = {(void*)&out};
    launch_pdl((void*)k_norm, dim3(NB_NORM), dim3(256), a3);
}

// round 13
// speedup vs baseline: 1.1340x; 1.0098x over previous
#include <cuda_runtime.h>
#include <math.h>

#define H 1024
#define S 65536
#define NB_VPART 128            // 8 rows of W each
#define NB_SCORES 8192          // 8 rows of enc each, TWO rows per warp
#define NB_NORM 256

// ---------------- scratch (no allocations allowed) ----------------
__device__ float    g_vpart[NB_VPART * H]; // 128 partial v vectors (512 KB)
__device__ float    g_v[H];                // v = W^T @ hidden
__device__ float    g_scores[S];           // raw scores
__device__ float2   g_bpart[NB_SCORES];    // per-CTA (max, sumexp)
__device__ unsigned g_Mu;                  // global max, order-encoded uint

// ordered-uint encoding of float (monotonic): deterministic atomicMax
__device__ __forceinline__ unsigned encf(float f) {
    unsigned b = __float_as_uint(f);
    return (b & 0x80000000u) ? ~b : (b | 0x80000000u);
}
__device__ __forceinline__ float decf(unsigned u) {
    unsigned b = (u & 0x80000000u) ? (u & 0x7fffffffu) : ~u;
    return __uint_as_float(b);
}

__device__ __forceinline__ float4 ldcs4(const float4* p) {
    return __ldcs(p);                     // streaming load (evict-first)
}

// =====================================================================
// kernel 1: partial v. 128 blocks x 256 thr; block b sums rows
// [8b, 8b+8). 8 independent float4 loads per thread (MLP=8).
// Also resets g_Mu for this graph replay (consumed 2 kernels later).
// =====================================================================
__global__ void __launch_bounds__(256) k_vpart(const float* __restrict__ hidden,
                                               const float* __restrict__ W) {
    int t  = threadIdx.x;                 // float4 column
    if (blockIdx.x == 0 && t == 0) g_Mu = 0u;   // enc(-inf) lower bound
    int r0 = blockIdx.x * 8;

    float h[8];
    float4 w[8];
#pragma unroll
    for (int i = 0; i < 8; i++) h[i] = __ldg(&hidden[r0 + i]);
#pragma unroll
    for (int i = 0; i < 8; i++)
        w[i] = ldcs4(reinterpret_cast<const float4*>(W + (size_t)(r0 + i) * H) + t);

    float4 acc = make_float4(0.f, 0.f, 0.f, 0.f);
#pragma unroll
    for (int i = 0; i < 8; i++) {
        acc.x += h[i] * w[i].x; acc.y += h[i] * w[i].y;
        acc.z += h[i] * w[i].z; acc.w += h[i] * w[i].w;
    }
    reinterpret_cast<float4*>(g_vpart + (size_t)blockIdx.x * H)[t] = acc;
}

// =====================================================================
// kernel 2: reduce 128 partials -> g_v. 16 blocks x 256 thr.  (PDL)
// =====================================================================
__global__ void __launch_bounds__(256) k_vreduce() {
#if __CUDA_ARCH__ >= 900
    cudaGridDependencySynchronize();
#endif
    __shared__ float4 sm[256];
    int t  = threadIdx.x;
    int c  = t & 15;                      // float4 col within block
    int pg = t >> 4;                      // partial group
    int col = (blockIdx.x * 16 + c);      // global float4 col [0,256)

    float4 acc = make_float4(0.f, 0.f, 0.f, 0.f);
#pragma unroll
    for (int p = pg; p < NB_VPART; p += 16) {     // 8 partials, MLP=8
        float4 x = reinterpret_cast<const float4*>(g_vpart)[(size_t)p * 256 + col];
        acc.x += x.x; acc.y += x.y; acc.z += x.z; acc.w += x.w;
    }
    sm[t] = acc;
    __syncthreads();
#pragma unroll
    for (int off = 128; off >= 16; off >>= 1) {
        if (t < off) {
            float4 a = sm[t], b = sm[t + off];
            a.x += b.x; a.y += b.y; a.z += b.z; a.w += b.w;
            sm[t] = a;
        }
        __syncthreads();
    }
    if (t < 16) reinterpret_cast<float4*>(g_v)[col] = sm[t];
}

// =====================================================================
// kernel 3: scores = enc @ v + per-block (m,s) + atomicMax global M.
// 8192 blocks x 128 thr, TWO rows per warp (8 rows/CTA) with all 16
// float4 loads issued up front (MLP=16) and BEFORE the grid-dependency
// sync. Smaller CTAs: finer tail granularity, 4-5 resident CTAs/SM,
// cheaper 4-warp barrier. Warp-level code identical to round 10.  (PDL)
// =====================================================================
__global__ void __launch_bounds__(128) k_scores(const float* __restrict__ enc) {
    __shared__ float4 sv[256];
    __shared__ float  rowv[8];
    int t = threadIdx.x;
    int warp = t >> 5, lane = t & 31;

    int row0 = (blockIdx.x << 3) + (warp << 1);         // this warp's 2 rows
    const float4* e0 = reinterpret_cast<const float4*>(enc + (size_t)row0 * H);
    const float4* e1 = e0 + (H / 4);

    // ---- prefetch BOTH rows (16 independent LDG.128, pre-sync) ----
    float4 a0 = ldcs4(e0 + 0 * 32 + lane);
    float4 a1 = ldcs4(e0 + 1 * 32 + lane);
    float4 a2 = ldcs4(e0 + 2 * 32 + lane);
    float4 a3 = ldcs4(e0 + 3 * 32 + lane);
    float4 a4 = ldcs4(e0 + 4 * 32 + lane);
    float4 a5 = ldcs4(e0 + 5 * 32 + lane);
    float4 a6 = ldcs4(e0 + 6 * 32 + lane);
    float4 a7 = ldcs4(e0 + 7 * 32 + lane);
    float4 c0 = ldcs4(e1 + 0 * 32 + lane);
    float4 c1 = ldcs4(e1 + 1 * 32 + lane);
    float4 c2 = ldcs4(e1 + 2 * 32 + lane);
    float4 c3 = ldcs4(e1 + 3 * 32 + lane);
    float4 c4 = ldcs4(e1 + 4 * 32 + lane);
    float4 c5 = ldcs4(e1 + 5 * 32 + lane);
    float4 c6 = ldcs4(e1 + 6 * 32 + lane);
    float4 c7 = ldcs4(e1 + 7 * 32 + lane);

#if __CUDA_ARCH__ >= 900
    cudaGridDependencySynchronize();      // now wait for g_v
#endif
    // 128 threads load 256 float4s of v (2 each)
    sv[t]       = reinterpret_cast<const float4*>(g_v)[t];
    sv[t + 128] = reinterpret_cast<const float4*>(g_v)[t + 128];
    __syncthreads();

    float acc0 = 0.f, acc1 = 0.f;
    {
        float4 b;
        b = sv[0 * 32 + lane];
        acc0 += a0.x*b.x + a0.y*b.y + a0.z*b.z + a0.w*b.w;
        acc1 += c0.x*b.x + c0.y*b.y + c0.z*b.z + c0.w*b.w;
        b = sv[1 * 32 + lane];
        acc0 += a1.x*b.x + a1.y*b.y + a1.z*b.z + a1.w*b.w;
        acc1 += c1.x*b.x + c1.y*b.y + c1.z*b.z + c1.w*b.w;
        b = sv[2 * 32 + lane];
        acc0 += a2.x*b.x + a2.y*b.y + a2.z*b.z + a2.w*b.w;
        acc1 += c2.x*b.x + c2.y*b.y + c2.z*b.z + c2.w*b.w;
        b = sv[3 * 32 + lane];
        acc0 += a3.x*b.x + a3.y*b.y + a3.z*b.z + a3.w*b.w;
        acc1 += c3.x*b.x + c3.y*b.y + c3.z*b.z + c3.w*b.w;
        b = sv[4 * 32 + lane];
        acc0 += a4.x*b.x + a4.y*b.y + a4.z*b.z + a4.w*b.w;
        acc1 += c4.x*b.x + c4.y*b.y + c4.z*b.z + c4.w*b.w;
        b = sv[5 * 32 + lane];
        acc0 += a5.x*b.x + a5.y*b.y + a5.z*b.z + a5.w*b.w;
        acc1 += c5.x*b.x + c5.y*b.y + c5.z*b.z + c5.w*b.w;
        b = sv[6 * 32 + lane];
        acc0 += a6.x*b.x + a6.y*b.y + a6.z*b.z + a6.w*b.w;
        acc1 += c6.x*b.x + c6.y*b.y + c6.z*b.z + c6.w*b.w;
        b = sv[7 * 32 + lane];
        acc0 += a7.x*b.x + a7.y*b.y + a7.z*b.z + a7.w*b.w;
        acc1 += c7.x*b.x + c7.y*b.y + c7.z*b.z + c7.w*b.w;
    }
#pragma unroll
    for (int o = 16; o; o >>= 1) {
        acc0 += __shfl_xor_sync(0xffffffffu, acc0, o);
        acc1 += __shfl_xor_sync(0xffffffffu, acc1, o);
    }
    if (lane == 0) {
        g_scores[row0]     = acc0;
        g_scores[row0 + 1] = acc1;
        rowv[(warp << 1)]     = acc0;
        rowv[(warp << 1) + 1] = acc1;
    }
    __syncthreads();

    // warp 0: block (m,s) over 8 row scores, lane-parallel
    if (warp == 0) {
        float x = (lane < 8) ? rowv[lane] : -INFINITY;
        float m = x;
#pragma unroll
        for (int o = 4; o; o >>= 1) m = fmaxf(m, __shfl_xor_sync(0xffffffffu, m, o));
        float p = (lane < 8) ? __expf(x - m) : 0.f;
#pragma unroll
        for (int o = 4; o; o >>= 1) p += __shfl_xor_sync(0xffffffffu, p, o);
        if (lane == 0) {
            g_bpart[blockIdx.x] = make_float2(m, p);
            atomicMax(&g_Mu, encf(m));    // order-independent => deterministic
        }
    }
}

// =====================================================================
// kernel 4: normalize. M from g_Mu; each of 256 blocks redundantly sums
// s_i*exp(m_i-M) over 8192 partials (32/thread, shfl, 2 barriers),
// then normalizes its 256-element slice (scalar coalesced).  (PDL)
// =====================================================================
__global__ void __launch_bounds__(256) k_norm(float* __restrict__ out) {
    __shared__ float swarp[8];
    __shared__ float sS;
    int t = threadIdx.x;
    int warp = t >> 5, lane = t & 31;
#if __CUDA_ARCH__ >= 900
    cudaGridDependencySynchronize();
#endif
    float M = decf(g_Mu);

    float s_loc = 0.f;
#pragma unroll 8
    for (int k = 0; k < NB_SCORES / 256; k++) {     // 32 partials per thread
        float2 p = g_bpart[k * 256 + t];
        s_loc += p.y * __expf(p.x - M);
    }
#pragma unroll
    for (int o = 16; o; o >>= 1) s_loc += __shfl_xor_sync(0xffffffffu, s_loc, o);
    if (lane == 0) swarp[warp] = s_loc;
    __syncthreads();
    if (warp == 0) {
        float v = (lane < 8) ? swarp[lane] : 0.f;
#pragma unroll
        for (int o = 4; o; o >>= 1) v += __shfl_xor_sync(0xffffffffu, v, o);
        if (lane == 0) sS = v;
    }
    __syncthreads();
    float inv = 1.f / sS;

    int i = blockIdx.x * 256 + t;                   // scalar, coalesced
    float s = g_scores[i];
    __stcs(&out[i], __expf(s - M) * inv);
}

// ---------------- launch (PDL on dependent edges) ----------------
static void launch_pdl(void* fn, dim3 grid, dim3 block, void** args) {
    cudaLaunchConfig_t cfg = {};
    cfg.gridDim = grid;
    cfg.blockDim = block;
    cfg.dynamicSmemBytes = 0;
    cfg.stream = 0;
    cudaLaunchAttribute attr[1];
    attr[0].id = cudaLaunchAttributeProgrammaticStreamSerialization;
    attr[0].val.programmaticStreamSerializationAllowed = 1;
    cfg.attrs = attr;
    cfg.numAttrs = 1;
    cudaLaunchKernelExC(&cfg, fn, args);
}

extern "C" void kernel_launch(void* const* d_in, const int* in_sizes, int n_in,
                              void* d_out, int out_size) {
    const float* hidden = (const float*)d_in[0];   // [H]
    const float* enc    = (const float*)d_in[1];   // [S, H]
    const float* W      = (const float*)d_in[2];   // [H, H]
    // d_in[3] = b : dropped — softmax is shift-invariant to b.hidden
    float* out = (float*)d_out;                    // [S]

    k_vpart<<<NB_VPART, 256>>>(hidden, W);

    void* a1[] = {};
    launch_pdl((void*)k_vreduce, dim3(16), dim3(256), a1);

    void* a2[] = {(void*)&enc};
    launch_pdl((void*)k_scores, dim3(NB_SCORES), dim3(128), a2);

    void* a3[] = {(void*)&out};
    launch_pdl((void*)k_norm, dim3(NB_NORM), dim3(256), a3);
}